// round 13
// baseline (speedup 1.0000x reference)
#include <cuda_runtime.h>

// Apply_Mask v13 — identical per-warp body to v12 (warp-per-slice, zero
// barriers/smem, fused packed-u64 argmax, __ldcs/__stcs, T-first early-out),
// repackaged as block=512 / grid=2048: same occupancy (2 CTAs/SM = 32 warps),
// half the CTAs — probing the measured wall-vs-grid-size trend
// (32768->44.42us, 8192->43.74, 4096->43.49).

#define H 32
#define W 32
#define HW 1024
#define WPC 16

__global__ void __launch_bounds__(32 * WPC, 2)
apply_mask_v13(const float* __restrict__ x,
               const int* __restrict__ T,
               const int* __restrict__ drop_block_ptr,
               float* __restrict__ out)
{
    const int warp = threadIdx.x >> 5;
    const int lane = threadIdx.x & 31;
    const int slice = blockIdx.x * WPC + warp;
    const size_t base = (size_t)slice * HW;

    const float4* __restrict__ xin = reinterpret_cast<const float4*>(x + base);
    float4* __restrict__ o = reinterpret_cast<float4*>(out + base);

    // T load first, overlapping the bulk loads below (warp-uniform value).
    const int t = __ldg(T + slice);

    // ---- front-batched bulk load: 8 x LDG.128, streaming ----
    float4 v[8];
#pragma unroll
    for (int j = 0; j < 8; j++)
        v[j] = __ldcs(xin + j * 32 + lane);

    if (t == 0) {
        // ---- copy path: stores depend only on loads ----
#pragma unroll
        for (int j = 0; j < 8; j++)
            __stcs(o + j * 32 + lane, v[j]);
        return;
    }

    // ---- local max, pairwise tree ----
    float m01 = fmaxf(fmaxf(fmaxf(v[0].x, v[0].y), fmaxf(v[0].z, v[0].w)),
                      fmaxf(fmaxf(v[1].x, v[1].y), fmaxf(v[1].z, v[1].w)));
    float m23 = fmaxf(fmaxf(fmaxf(v[2].x, v[2].y), fmaxf(v[2].z, v[2].w)),
                      fmaxf(fmaxf(v[3].x, v[3].y), fmaxf(v[3].z, v[3].w)));
    float m45 = fmaxf(fmaxf(fmaxf(v[4].x, v[4].y), fmaxf(v[4].z, v[4].w)),
                      fmaxf(fmaxf(v[5].x, v[5].y), fmaxf(v[5].z, v[5].w)));
    float m67 = fmaxf(fmaxf(fmaxf(v[6].x, v[6].y), fmaxf(v[6].z, v[6].w)),
                      fmaxf(fmaxf(v[7].x, v[7].y), fmaxf(v[7].z, v[7].w)));
    const float m = fmaxf(fmaxf(m01, m23), fmaxf(m45, m67));

    // ---- local first-occurrence index of m ----
    unsigned lidx = HW;
    {
        const float* vf = &v[0].x;
#pragma unroll
        for (int j = 0; j < 8; j++) {
#pragma unroll
            for (int i = 0; i < 4; i++) {
                const unsigned e = (unsigned)(j * 128 + lane * 4 + i);
                if (vf[j * 4 + i] == m) lidx = min(lidx, e);
            }
        }
    }

    // ---- pack (ordered value, inverted index); 5-shuffle max-reduce =>
    //      argmax with first-occurrence tie-break. No barriers, no smem. ----
    unsigned u = __float_as_uint(m);
    unsigned okey = u ^ (unsigned)(((int)u >> 31) | 0x80000000);
    unsigned long long best =
        ((unsigned long long)okey << 32) | (unsigned)(HW - 1 - lidx);

#pragma unroll
    for (int off = 16; off > 0; off >>= 1) {
        unsigned long long ob = __shfl_xor_sync(0xffffffffu, best, off);
        if (ob > best) best = ob;
    }

    const unsigned idx = (unsigned)(HW - 1) - (unsigned)(best & 0xffffffffu);

    // ---- box + lambda ----
    const int mh = (int)(idx >> 5);
    const int mw = (int)(idx & (W - 1));
    const int db = drop_block_ptr ? *drop_block_ptr : 5;
    const int half = db >> 1;

    const int h1 = max(mh - half, 0);
    const int h2 = min(mh + half, H - 1);
    const int w1 = max(mw - half, 0);
    const int w2 = min(mw + half, W - 1);

    const int area = (h2 - h1 + 1) * (w2 - w1 + 1);
    const float lam = (float)HW / (float)(HW - area);

    // element e = j*128 + lane*4 + i -> row = j*4 + (lane>>3),
    //                                   col = (lane&7)*4 + i
    const int rbase = lane >> 3;
    const int cbase = (lane & 7) * 4;

    bool in_col[4];
#pragma unroll
    for (int i = 0; i < 4; i++)
        in_col[i] = (unsigned)(cbase + i - w1) <= (unsigned)(w2 - w1);

    float row_scale[8];  // scale when in_col true: 0 inside box, lam outside
#pragma unroll
    for (int j = 0; j < 8; j++) {
        const int r = j * 4 + rbase;
        const bool in_row = (unsigned)(r - h1) <= (unsigned)(h2 - h1);
        row_scale[j] = in_row ? 0.0f : lam;
    }

    // ---- scale + store ----
#pragma unroll
    for (int j = 0; j < 8; j++) {
        float4 w4;
        w4.x = v[j].x * (in_col[0] ? row_scale[j] : lam);
        w4.y = v[j].y * (in_col[1] ? row_scale[j] : lam);
        w4.z = v[j].z * (in_col[2] ? row_scale[j] : lam);
        w4.w = v[j].w * (in_col[3] ? row_scale[j] : lam);
        __stcs(o + j * 32 + lane, w4);
    }
}

extern "C" void kernel_launch(void* const* d_in, const int* in_sizes, int n_in,
                              void* d_out, int out_size)
{
    const float* x = (const float*)d_in[0];
    const int* T = (const int*)d_in[1];
    const int* db = (n_in >= 3) ? (const int*)d_in[2] : nullptr;
    float* out = (float*)d_out;

    const int n_slices = in_sizes[0] / HW;   // 32768
    const int n_ctas = n_slices / WPC;       // 2048

    apply_mask_v13<<<n_ctas, 32 * WPC>>>(x, T, db, out);
}

// round 14
// speedup vs baseline: 1.0079x; 1.0079x over previous
#include <cuda_runtime.h>

// Apply_Mask FINAL (= v12, best measured: 43.488us wall, reproduced twice).
// Warp-per-slice, grid=4096 x block=256. Per warp: T loaded first (in flight
// with 8 front-batched streaming LDG.128), T==0 warps (~half) take a pure
// copy path; else fused packed-u64 argmax (5 shuffles, zero barriers/smem),
// clipped 5x5 drop-box, lambda rescale, streaming STG.128.
// Kernel is pinned at the mixed read+write HBM roofline (~6TB/s, ~74% of
// spec) — verified invariant across occupancy 36-87%, block 64-512, all
// cache policies, and three reduction structures (rounds 1-13).

#define H 32
#define W 32
#define HW 1024
#define WPC 8

__global__ void __launch_bounds__(32 * WPC, 4)
apply_mask_final(const float* __restrict__ x,
                 const int* __restrict__ T,
                 const int* __restrict__ drop_block_ptr,
                 float* __restrict__ out)
{
    const int warp = threadIdx.x >> 5;
    const int lane = threadIdx.x & 31;
    const int slice = blockIdx.x * WPC + warp;
    const size_t base = (size_t)slice * HW;

    const float4* __restrict__ xin = reinterpret_cast<const float4*>(x + base);
    float4* __restrict__ o = reinterpret_cast<float4*>(out + base);

    // T load first, overlapping the bulk loads below (warp-uniform value).
    const int t = __ldg(T + slice);

    // ---- front-batched bulk load: 8 x LDG.128, streaming ----
    float4 v[8];
#pragma unroll
    for (int j = 0; j < 8; j++)
        v[j] = __ldcs(xin + j * 32 + lane);

    if (t == 0) {
        // ---- copy path: stores depend only on loads ----
#pragma unroll
        for (int j = 0; j < 8; j++)
            __stcs(o + j * 32 + lane, v[j]);
        return;
    }

    // ---- local max, pairwise tree ----
    float m01 = fmaxf(fmaxf(fmaxf(v[0].x, v[0].y), fmaxf(v[0].z, v[0].w)),
                      fmaxf(fmaxf(v[1].x, v[1].y), fmaxf(v[1].z, v[1].w)));
    float m23 = fmaxf(fmaxf(fmaxf(v[2].x, v[2].y), fmaxf(v[2].z, v[2].w)),
                      fmaxf(fmaxf(v[3].x, v[3].y), fmaxf(v[3].z, v[3].w)));
    float m45 = fmaxf(fmaxf(fmaxf(v[4].x, v[4].y), fmaxf(v[4].z, v[4].w)),
                      fmaxf(fmaxf(v[5].x, v[5].y), fmaxf(v[5].z, v[5].w)));
    float m67 = fmaxf(fmaxf(fmaxf(v[6].x, v[6].y), fmaxf(v[6].z, v[6].w)),
                      fmaxf(fmaxf(v[7].x, v[7].y), fmaxf(v[7].z, v[7].w)));
    const float m = fmaxf(fmaxf(m01, m23), fmaxf(m45, m67));

    // ---- local first-occurrence index of m ----
    unsigned lidx = HW;
    {
        const float* vf = &v[0].x;
#pragma unroll
        for (int j = 0; j < 8; j++) {
#pragma unroll
            for (int i = 0; i < 4; i++) {
                const unsigned e = (unsigned)(j * 128 + lane * 4 + i);
                if (vf[j * 4 + i] == m) lidx = min(lidx, e);
            }
        }
    }

    // ---- pack (ordered value, inverted index); 5-shuffle max-reduce =>
    //      argmax with first-occurrence tie-break. No barriers, no smem. ----
    unsigned u = __float_as_uint(m);
    unsigned okey = u ^ (unsigned)(((int)u >> 31) | 0x80000000);
    unsigned long long best =
        ((unsigned long long)okey << 32) | (unsigned)(HW - 1 - lidx);

#pragma unroll
    for (int off = 16; off > 0; off >>= 1) {
        unsigned long long ob = __shfl_xor_sync(0xffffffffu, best, off);
        if (ob > best) best = ob;
    }

    const unsigned idx = (unsigned)(HW - 1) - (unsigned)(best & 0xffffffffu);

    // ---- box + lambda ----
    const int mh = (int)(idx >> 5);
    const int mw = (int)(idx & (W - 1));
    const int db = drop_block_ptr ? *drop_block_ptr : 5;
    const int half = db >> 1;

    const int h1 = max(mh - half, 0);
    const int h2 = min(mh + half, H - 1);
    const int w1 = max(mw - half, 0);
    const int w2 = min(mw + half, W - 1);

    const int area = (h2 - h1 + 1) * (w2 - w1 + 1);
    const float lam = (float)HW / (float)(HW - area);

    // element e = j*128 + lane*4 + i -> row = j*4 + (lane>>3),
    //                                   col = (lane&7)*4 + i
    const int rbase = lane >> 3;
    const int cbase = (lane & 7) * 4;

    bool in_col[4];
#pragma unroll
    for (int i = 0; i < 4; i++)
        in_col[i] = (unsigned)(cbase + i - w1) <= (unsigned)(w2 - w1);

    float row_scale[8];  // scale when in_col true: 0 inside box, lam outside
#pragma unroll
    for (int j = 0; j < 8; j++) {
        const int r = j * 4 + rbase;
        const bool in_row = (unsigned)(r - h1) <= (unsigned)(h2 - h1);
        row_scale[j] = in_row ? 0.0f : lam;
    }

    // ---- scale + store ----
#pragma unroll
    for (int j = 0; j < 8; j++) {
        float4 w4;
        w4.x = v[j].x * (in_col[0] ? row_scale[j] : lam);
        w4.y = v[j].y * (in_col[1] ? row_scale[j] : lam);
        w4.z = v[j].z * (in_col[2] ? row_scale[j] : lam);
        w4.w = v[j].w * (in_col[3] ? row_scale[j] : lam);
        __stcs(o + j * 32 + lane, w4);
    }
}

extern "C" void kernel_launch(void* const* d_in, const int* in_sizes, int n_in,
                              void* d_out, int out_size)
{
    const float* x = (const float*)d_in[0];
    const int* T = (const int*)d_in[1];
    const int* db = (n_in >= 3) ? (const int*)d_in[2] : nullptr;
    float* out = (float*)d_out;

    const int n_slices = in_sizes[0] / HW;   // 32768
    const int n_ctas = n_slices / WPC;       // 4096

    apply_mask_final<<<n_ctas, 32 * WPC>>>(x, T, db, out);
}